// round 11
// baseline (speedup 1.0000x reference)
#include <cuda_runtime.h>
#include <cuda_fp16.h>
#include <cstdint>

// ============================================================================
// Problem constants
// ============================================================================
#define T_TOK   8192          // B*S tokens
#define HDIM    2048
#define NEXP    8
#define NSLOTS  17408         // 2*T + 8*128 padding
#define MAX_TILES 136
#define KCAT    4096          // merged K: [xh | u] / [wh | 32v]
#define KSTEPS  128           // KCAT / 32 per k-step

// ============================================================================
// PTX helpers — family-portable only (mma.sync / ldmatrix / cp.async)
// ============================================================================
__device__ __forceinline__ uint32_t smem_to_u32(const void* p) {
    uint32_t a;
    asm("{ .reg .u64 t; cvta.to.shared.u64 t, %1; cvt.u32.u64 %0, t; }"
        : "=r"(a) : "l"(p));
    return a;
}

#define CP_ASYNC16(smem, gmem) \
    asm volatile("cp.async.cg.shared.global [%0], [%1], 16;" \
        :: "r"(smem), "l"(gmem))
#define CP_COMMIT() asm volatile("cp.async.commit_group;" ::: "memory")
#define CP_WAIT2()  asm volatile("cp.async.wait_group 2;" ::: "memory")

__device__ __forceinline__ void ldsm_x4(uint32_t* r, uint32_t addr) {
    asm volatile("ldmatrix.sync.aligned.m8n8.x4.shared.b16 {%0,%1,%2,%3}, [%4];"
        : "=r"(r[0]), "=r"(r[1]), "=r"(r[2]), "=r"(r[3]) : "r"(addr));
}

// m16n8k16 fp16 HMMA, fp32 accumulate
__device__ __forceinline__ void mma16816(float* d, const uint32_t* a,
                                         const uint32_t* b) {
    asm volatile(
        "mma.sync.aligned.m16n8k16.row.col.f32.f16.f16.f32 "
        "{%0,%1,%2,%3}, {%4,%5,%6,%7}, {%8,%9}, {%0,%1,%2,%3};"
        : "+f"(d[0]), "+f"(d[1]), "+f"(d[2]), "+f"(d[3])
        : "r"(a[0]), "r"(a[1]), "r"(a[2]), "r"(a[3]), "r"(b[0]), "r"(b[1]));
}

// SW64 swizzle: XOR byte-offset bits[5:4] with bits[8:7] (row bits for 64B rows)
#define SW64(off) ((off) ^ (((off) >> 3) & 0x30))

// ============================================================================
// Device scratch
// ============================================================================
__device__ int    g_count[NEXP];
__device__ int    g_cursor[NEXP];
__device__ int    g_base[NEXP];
__device__ int    g_tile_expert[MAX_TILES];
__device__ int    g_tile_mbase[MAX_TILES];
__device__ int    g_num_tiles;
__device__ int    g_topi[T_TOK * 2];
__device__ float  g_topw[T_TOK * 2];
__device__ int    g_slot_token[NSLOTS];    // zero-init; stale values stay in
__device__ float  g_slot_w[NSLOTS];        //   [0,T); w cleared each launch

__device__ __half g_xc[(size_t)T_TOK * KCAT];              // 67 MB [xh | u], per TOKEN
__device__ __half g_wc[(size_t)NEXP * HDIM * KCAT];        // 134 MB [wh | 32v]

// ============================================================================
// K0: reset counters + clear slot weights (padding slots must contribute 0
// to the output atomics; stale tokens are harmless once w == 0).
// ============================================================================
__global__ void moe_init_kernel() {
    int i = blockIdx.x * blockDim.x + threadIdx.x;
    if (i < NEXP) { g_count[i] = 0; g_cursor[i] = 0; }
    if (i < NSLOTS) g_slot_w[i] = 0.0f;
}

// ============================================================================
// K1: zero the output region the GEMM will atomically accumulate into.
// (logits tail is written by the router, not zeroed here)
// ============================================================================
__global__ void moe_zero_out_kernel(float4* __restrict__ out4) {
    int i = blockIdx.x * blockDim.x + threadIdx.x;   // T*H/4 float4s
    out4[i] = make_float4(0.f, 0.f, 0.f, 0.f);
}

// ============================================================================
// K2: router — logits + top-2 normalized weights. One warp per token.
// ============================================================================
__global__ void moe_router_kernel(const float* __restrict__ x,
                                  const float* __restrict__ gw,
                                  float* __restrict__ logits_out) {
    int warp = (blockIdx.x * blockDim.x + threadIdx.x) >> 5;
    int lane = threadIdx.x & 31;
    if (warp >= T_TOK) return;
    const float4* xr = (const float4*)(x + (size_t)warp * HDIM);
    float acc[NEXP];
#pragma unroll
    for (int e = 0; e < NEXP; e++) acc[e] = 0.f;
    for (int i = lane; i < HDIM / 4; i += 32) {
        float4 xv = xr[i];
#pragma unroll
        for (int e = 0; e < NEXP; e++) {
            float4 gv = ((const float4*)(gw + e * HDIM))[i];
            acc[e] += xv.x * gv.x + xv.y * gv.y + xv.z * gv.z + xv.w * gv.w;
        }
    }
#pragma unroll
    for (int e = 0; e < NEXP; e++)
#pragma unroll
        for (int off = 16; off; off >>= 1)
            acc[e] += __shfl_xor_sync(0xFFFFFFFFu, acc[e], off);
    if (lane == 0) {
#pragma unroll
        for (int e = 0; e < NEXP; e++) logits_out[warp * NEXP + e] = acc[e];
        int i1 = 0; float l1 = acc[0];
#pragma unroll
        for (int e = 1; e < NEXP; e++) if (acc[e] > l1) { l1 = acc[e]; i1 = e; }
        int i2 = -1; float l2 = -3.4e38f;
#pragma unroll
        for (int e = 0; e < NEXP; e++)
            if (e != i1 && acc[e] > l2) { l2 = acc[e]; i2 = e; }
        float ex = expf(l2 - l1);
        float w1 = 1.0f / (1.0f + ex);
        float w2 = ex / (1.0f + ex);
        g_topi[warp * 2 + 0] = i1;  g_topw[warp * 2 + 0] = w1;
        g_topi[warp * 2 + 1] = i2;  g_topw[warp * 2 + 1] = w2;
        atomicAdd(&g_count[i1], 1);
        atomicAdd(&g_count[i2], 1);
    }
}

// ============================================================================
// K3: serial scan — padded slot bases + tile map
// ============================================================================
__global__ void moe_scan_kernel() {
    if (threadIdx.x == 0 && blockIdx.x == 0) {
        int run = 0, nt = 0;
        for (int e = 0; e < NEXP; e++) {
            g_base[e] = run;
            int c = g_count[e];
            int tiles = (c + 127) >> 7;
            for (int t = 0; t < tiles; t++) {
                g_tile_expert[nt] = e;
                g_tile_mbase[nt]  = run + t * 128;
                nt++;
            }
            run += tiles << 7;
        }
        g_num_tiles = nt;
    }
}

// ============================================================================
// K4: scatter tokens into per-expert slot lists
// ============================================================================
__global__ void moe_assign_kernel() {
    int t = blockIdx.x * blockDim.x + threadIdx.x;
    if (t >= T_TOK) return;
#pragma unroll
    for (int k = 0; k < 2; k++) {
        int e = g_topi[t * 2 + k];
        int pos = atomicAdd(&g_cursor[e], 1);
        int slot = g_base[e] + pos;
        g_slot_token[slot] = t;
        g_slot_w[slot] = g_topw[t * 2 + k];
    }
}

// ============================================================================
// K5: split-convert (Ootomo, merged-K layout). x stored per TOKEN (GEMM
// gathers rows through slot_token at fill time).
//   A row (4096): [ xh = fp16(x) | u = fp16(xh/32 + (x-xh)) ]
//   B row (4096): [ wh = fp16(64w) | 32*fp16(wh/32 + (64w-wh)) ]  (32x exact)
// ============================================================================
#define XBLK (T_TOK * 512 / 256)                  // 16384
#define WBLK (NEXP * HDIM * HDIM / 4 / 256)       // 32768

__device__ __forceinline__ void split2(float a, float b, uint32_t& h,
                                       uint32_t& u, float post) {
    __half2 hh = __floats2half2_rn(a, b);
    float2 hf = __half22float2(hh);
    __half2 uu = __floats2half2_rn((hf.x * 0.03125f + (a - hf.x)) * post,
                                   (hf.y * 0.03125f + (b - hf.y)) * post);
    h = *(uint32_t*)&hh;
    u = *(uint32_t*)&uu;
}

__global__ void moe_convert_kernel(const float* __restrict__ x,
                                   const float* __restrict__ ew) {
    if (blockIdx.x < XBLK) {
        int i = blockIdx.x * 256 + threadIdx.x;
        int tok = i >> 9;
        int j = i & 511;
        float4 vv = ((const float4*)x)[(size_t)tok * 512 + j];
        uint32_t h0, u0, h1, u1;
        split2(vv.x, vv.y, h0, u0, 1.0f);
        split2(vv.z, vv.w, h1, u1, 1.0f);
        size_t rb = (size_t)tok * (KCAT / 4);           // uint2 units per row
        ((uint2*)g_xc)[rb + j]       = make_uint2(h0, h1);
        ((uint2*)g_xc)[rb + 512 + j] = make_uint2(u0, u1);
    } else {
        size_t i = (size_t)(blockIdx.x - XBLK) * 256 + threadIdx.x;
        int row = (int)(i >> 9);                        // e*HDIM + n
        int j = (int)(i & 511);
        float4 vv = ((const float4*)ew)[i];
        uint32_t h0, u0, h1, u1;
        // post=32 scales the correction term exactly (power of 2 in fp16)
        split2(vv.x * 64.f, vv.y * 64.f, h0, u0, 32.0f);
        split2(vv.z * 64.f, vv.w * 64.f, h1, u1, 32.0f);
        size_t rb = (size_t)row * (KCAT / 4);
        ((uint2*)g_wc)[rb + j]       = make_uint2(h0, h1);
        ((uint2*)g_wc)[rb + 512 + j] = make_uint2(u0, u1);
    }
}

// ============================================================================
// K6: grouped GEMM — 128x128xK4096 merged Ootomo, single fp32 acc set,
// 4 warps (2x2 grid, 64x64 warp tile), 2 CTAs/SM, 4-stage cp.async, SW64.
// Epilogue: atomicAdd (RED.F32) weighted rows directly into out[token] —
// each output element receives exactly TWO contributions (fp32 add of two
// terms is commutative => bitwise deterministic). Padding slots have w==0
// and are skipped.
// Mid-loop: acc *= 31/32 (fp32-exact) between the xh*wh and u*32v halves.
// ============================================================================
#define MAT_B     8192                        // 128 rows x 64B
#define STAGE_B   (2 * MAT_B)                 // 16384 (A, B)
#define NSTAGE    4
#define SMEM_DYN  (1024 + NSTAGE * STAGE_B)   // 66560 B -> 2 CTAs/SM

__global__ void __launch_bounds__(128, 2)
moe_gemm_kernel(float* __restrict__ out) {
    int tile = blockIdx.y;
    if (tile >= g_num_tiles) return;
    int n0    = blockIdx.x * 128;
    int e     = g_tile_expert[tile];
    int mbase = g_tile_mbase[tile];

    extern __shared__ char dsm[];
    float* s_fr    = (float*)dsm;             // 128: slotw/64 per row
    int*   s_token = (int*)(dsm + 512);       // 128: token per row
    uint32_t st0 = smem_to_u32(dsm) + 1024;

    int tid = threadIdx.x, lane = tid & 31, wid = tid >> 5;
    int wm = wid >> 1, wn = wid & 1;          // 2x2 grid, warp 64(M)x64(N)

    if (tid < 128) {
        s_fr[tid]    = g_slot_w[mbase + tid] * (1.0f / 64.0f);
        s_token[tid] = g_slot_token[mbase + tid];
    }
    __syncthreads();

    const __half* Bg = g_wc + ((size_t)e * HDIM + n0) * KCAT;

    // precompute per-thread fill pointers (8 chunks: 4 A via token gather, 4 B)
    const __half* gsrc[8];
    uint32_t sdst[8];
#pragma unroll
    for (int i = 0; i < 8; i++) {
        int cid = tid + i * 128;
        int mat = cid >> 9;                   // 0=A, 1=B
        int win = cid & 511;
        int rr  = win >> 2;
        int cc  = win & 3;
        if (mat == 0) {
            int tok = s_token[rr];
            gsrc[i] = g_xc + (size_t)tok * KCAT + cc * 8;
        } else {
            gsrc[i] = Bg + (size_t)rr * KCAT + cc * 8;
        }
        sdst[i] = st0 + mat * MAT_B + SW64((uint32_t)(rr * 64 + cc * 16));
    }

    auto fill = [&](int stage, int kt) {
        uint32_t so = (uint32_t)(stage * STAGE_B);
        int k0 = kt * 32;
#pragma unroll
        for (int i = 0; i < 8; i++)
            CP_ASYNC16(sdst[i] + so, gsrc[i] + k0);
    };

    fill(0, 0); CP_COMMIT();
    fill(1, 1); CP_COMMIT();
    fill(2, 2); CP_COMMIT();

    float acc[4][8][4];
#pragma unroll
    for (int a = 0; a < 4; a++)
#pragma unroll
        for (int b = 0; b < 8; b++)
#pragma unroll
            for (int c = 0; c < 4; c++) acc[a][b][c] = 0.f;

    for (int kt = 0; kt < KSTEPS; kt++) {
        // between halves: acc = T1 -> scale by 31/32 (fp32-exact cancellation)
        if (kt == KSTEPS / 2) {
#pragma unroll
            for (int a = 0; a < 4; a++)
#pragma unroll
                for (int b = 0; b < 8; b++)
#pragma unroll
                    for (int c = 0; c < 4; c++) acc[a][b][c] *= 0.96875f;
        }
        CP_WAIT2();
        __syncthreads();                      // single sync per k-step

        int nxt = kt + 3;                     // stage (kt+3)&3 was read in kt-1
        if (nxt < KSTEPS) fill(nxt & 3, nxt);
        CP_COMMIT();

        uint32_t sbase = st0 + (kt & 3) * STAGE_B;
        uint32_t sA = sbase, sB = sbase + MAT_B;
#pragma unroll
        for (int k16 = 0; k16 < 2; k16++) {
            uint32_t af[4][4];
#pragma unroll
            for (int mi = 0; mi < 4; mi++) {
                uint32_t ad = SW64((uint32_t)(
                    (wm * 64 + mi * 16 + (lane & 15)) * 64
                    + k16 * 32 + (lane >> 4) * 16));
                ldsm_x4(af[mi], sA + ad);
            }
            uint32_t bf[4][4];
#pragma unroll
            for (int jj = 0; jj < 4; jj++) {
                uint32_t bd = SW64((uint32_t)(
                    (wn * 64 + jj * 16 + ((lane >> 4) << 3) + (lane & 7)) * 64
                    + k16 * 32 + (((lane >> 3) & 1) << 4)));
                ldsm_x4(bf[jj], sB + bd);
            }
            // 32 HMMAs per k16, acc reuse distance 32
#pragma unroll
            for (int mi = 0; mi < 4; mi++)
#pragma unroll
                for (int jj = 0; jj < 4; jj++)
#pragma unroll
                    for (int s = 0; s < 2; s++)
                        mma16816(acc[mi][jj * 2 + s], af[mi], &bf[jj][s * 2]);
        }
    }

    // epilogue: RED.F32 weighted rows straight into out[token]
#pragma unroll
    for (int mi = 0; mi < 4; mi++) {
        int r0 = wm * 64 + mi * 16 + (lane >> 2);
        float f0 = s_fr[r0], f1 = s_fr[r0 + 8];
        size_t o0 = (size_t)s_token[r0] * HDIM + n0;
        size_t o1 = (size_t)s_token[r0 + 8] * HDIM + n0;
#pragma unroll
        for (int n8 = 0; n8 < 8; n8++) {
            int c = wn * 64 + n8 * 8 + (lane & 3) * 2;
            if (f0 != 0.0f) {
                atomicAdd(&out[o0 + c],     acc[mi][n8][0] * f0);
                atomicAdd(&out[o0 + c + 1], acc[mi][n8][1] * f0);
            }
            if (f1 != 0.0f) {
                atomicAdd(&out[o1 + c],     acc[mi][n8][2] * f1);
                atomicAdd(&out[o1 + c + 1], acc[mi][n8][3] * f1);
            }
        }
    }
}

// ============================================================================
// Launch
// ============================================================================
extern "C" void kernel_launch(void* const* d_in, const int* in_sizes, int n_in,
                              void* d_out, int out_size) {
    const float* x  = (const float*)d_in[0];   // hidden_states [T, H]
    const float* gw = (const float*)d_in[1];   // gate_w [E, H]
    const float* ew = (const float*)d_in[2];   // expert_w [E, H, H]
    float* out    = (float*)d_out;             // [T, H]
    float* logits = out + (size_t)T_TOK * HDIM;

    cudaFuncSetAttribute(moe_gemm_kernel,
                         cudaFuncAttributeMaxDynamicSharedMemorySize, SMEM_DYN);

    moe_init_kernel<<<NSLOTS / 256, 256>>>();
    moe_zero_out_kernel<<<(T_TOK * HDIM / 4) / 256, 256>>>((float4*)out);
    moe_router_kernel<<<(T_TOK * 32) / 256, 256>>>(x, gw, logits);
    moe_scan_kernel<<<1, 32>>>();
    moe_assign_kernel<<<T_TOK / 256, 256>>>();
    moe_convert_kernel<<<XBLK + WBLK, 256>>>(x, ew);
    moe_gemm_kernel<<<dim3(16, MAX_TILES), 128, SMEM_DYN>>>(out);
}

// round 12
// speedup vs baseline: 1.0254x; 1.0254x over previous
#include <cuda_runtime.h>
#include <cuda_fp16.h>
#include <cstdint>

// ============================================================================
// Problem constants
// ============================================================================
#define T_TOK   8192          // B*S tokens
#define HDIM    2048
#define NEXP    8
#define MAX_TILES 136         // sum ceil(count_e/128) <= 2T/128 + E
#define KCAT    4096          // merged K: [xh | u] / [wh | 32v]
#define KSTEPS  128           // KCAT / 32 per k-step
#define NSLOTF  (NEXP * T_TOK)   // fixed-capacity slot space (65536)

// ============================================================================
// PTX helpers — family-portable only (mma.sync / ldmatrix / cp.async)
// ============================================================================
__device__ __forceinline__ uint32_t smem_to_u32(const void* p) {
    uint32_t a;
    asm("{ .reg .u64 t; cvta.to.shared.u64 t, %1; cvt.u32.u64 %0, t; }"
        : "=r"(a) : "l"(p));
    return a;
}

#define CP_ASYNC16(smem, gmem) \
    asm volatile("cp.async.cg.shared.global [%0], [%1], 16;" \
        :: "r"(smem), "l"(gmem))
#define CP_COMMIT() asm volatile("cp.async.commit_group;" ::: "memory")
#define CP_WAIT2()  asm volatile("cp.async.wait_group 2;" ::: "memory")

__device__ __forceinline__ void ldsm_x4(uint32_t* r, uint32_t addr) {
    asm volatile("ldmatrix.sync.aligned.m8n8.x4.shared.b16 {%0,%1,%2,%3}, [%4];"
        : "=r"(r[0]), "=r"(r[1]), "=r"(r[2]), "=r"(r[3]) : "r"(addr));
}

// m16n8k16 fp16 HMMA, fp32 accumulate
__device__ __forceinline__ void mma16816(float* d, const uint32_t* a,
                                         const uint32_t* b) {
    asm volatile(
        "mma.sync.aligned.m16n8k16.row.col.f32.f16.f16.f32 "
        "{%0,%1,%2,%3}, {%4,%5,%6,%7}, {%8,%9}, {%0,%1,%2,%3};"
        : "+f"(d[0]), "+f"(d[1]), "+f"(d[2]), "+f"(d[3])
        : "r"(a[0]), "r"(a[1]), "r"(a[2]), "r"(a[3]), "r"(b[0]), "r"(b[1]));
}

// SW64 swizzle: XOR byte-offset bits[5:4] with bits[8:7] (row bits for 64B rows)
#define SW64(off) ((off) ^ (((off) >> 3) & 0x30))

// ============================================================================
// Device scratch — fixed-capacity slot layout: slot = e*T_TOK + pos.
// g_cursor must be 0 on entry of every launch: zero-init covers call 1;
// the combine kernel clears it at the end of each launch (graph-replay safe,
// deterministic — routing depends only on inputs).
// ============================================================================
__device__ int    g_cursor[NEXP];
__device__ int    g_tile_expert[MAX_TILES];
__device__ int    g_tile_mbase[MAX_TILES];
__device__ int    g_num_tiles;
__device__ int    g_slot_token[NSLOTF];    // zero-init; stale values stay in
__device__ float  g_slot_w[NSLOTF];        //   [0,T) so always a valid index
__device__ int    g_tok_slot[T_TOK * 2];

__device__ __half g_xc[(size_t)T_TOK * KCAT];              // 67 MB [xh | u], per TOKEN
__device__ __half g_wc[(size_t)NEXP * HDIM * KCAT];        // 134 MB [wh | 32v]
__device__ float  g_ybuf[(size_t)NSLOTF * HDIM];           // 536 MB, sparse-written

// ============================================================================
// K1: router — logits + top-2 normalized weights + DIRECT slot assignment
// (fixed per-expert regions, no scan needed). One warp per token.
// ============================================================================
__global__ void moe_router_kernel(const float* __restrict__ x,
                                  const float* __restrict__ gw,
                                  float* __restrict__ logits_out) {
    int warp = (blockIdx.x * blockDim.x + threadIdx.x) >> 5;
    int lane = threadIdx.x & 31;
    if (warp >= T_TOK) return;
    const float4* xr = (const float4*)(x + (size_t)warp * HDIM);
    float acc[NEXP];
#pragma unroll
    for (int e = 0; e < NEXP; e++) acc[e] = 0.f;
    for (int i = lane; i < HDIM / 4; i += 32) {
        float4 xv = xr[i];
#pragma unroll
        for (int e = 0; e < NEXP; e++) {
            float4 gv = ((const float4*)(gw + e * HDIM))[i];
            acc[e] += xv.x * gv.x + xv.y * gv.y + xv.z * gv.z + xv.w * gv.w;
        }
    }
#pragma unroll
    for (int e = 0; e < NEXP; e++)
#pragma unroll
        for (int off = 16; off; off >>= 1)
            acc[e] += __shfl_xor_sync(0xFFFFFFFFu, acc[e], off);
    if (lane == 0) {
#pragma unroll
        for (int e = 0; e < NEXP; e++) logits_out[warp * NEXP + e] = acc[e];
        int i1 = 0; float l1 = acc[0];
#pragma unroll
        for (int e = 1; e < NEXP; e++) if (acc[e] > l1) { l1 = acc[e]; i1 = e; }
        int i2 = -1; float l2 = -3.4e38f;
#pragma unroll
        for (int e = 0; e < NEXP; e++)
            if (e != i1 && acc[e] > l2) { l2 = acc[e]; i2 = e; }
        float ex = expf(l2 - l1);
        float w1 = 1.0f / (1.0f + ex);
        float w2 = ex / (1.0f + ex);
        // fused assign: fixed-capacity regions, base[e] = e*T_TOK
        int p1 = atomicAdd(&g_cursor[i1], 1);
        int s1 = i1 * T_TOK + p1;
        g_slot_token[s1] = warp;  g_slot_w[s1] = w1;  g_tok_slot[warp * 2] = s1;
        int p2 = atomicAdd(&g_cursor[i2], 1);
        int s2 = i2 * T_TOK + p2;
        g_slot_token[s2] = warp;  g_slot_w[s2] = w2;  g_tok_slot[warp * 2 + 1] = s2;
    }
}

// ============================================================================
// K2: split-convert (Ootomo, merged-K layout) + tile-map scan in block 0.
//   A row (4096): [ xh = fp16(x) | u = fp16(xh/32 + (x-xh)) ]
//   B row (4096): [ wh = fp16(64w) | 32*fp16(wh/32 + (64w-wh)) ]  (32x exact)
// Block 0 thread 0 additionally builds the compact tile map from g_cursor
// (fully hidden under ~49k converting blocks; GEMM launch sees it).
// ============================================================================
#define XBLK (T_TOK * 512 / 256)                  // 16384
#define WBLK (NEXP * HDIM * HDIM / 4 / 256)       // 32768

__device__ __forceinline__ void split2(float a, float b, uint32_t& h,
                                       uint32_t& u, float post) {
    __half2 hh = __floats2half2_rn(a, b);
    float2 hf = __half22float2(hh);
    __half2 uu = __floats2half2_rn((hf.x * 0.03125f + (a - hf.x)) * post,
                                   (hf.y * 0.03125f + (b - hf.y)) * post);
    h = *(uint32_t*)&hh;
    u = *(uint32_t*)&uu;
}

__global__ void moe_convert_kernel(const float* __restrict__ x,
                                   const float* __restrict__ ew) {
    if (blockIdx.x == 0 && threadIdx.x == 0) {
        int nt = 0;
        for (int e = 0; e < NEXP; e++) {
            int c = g_cursor[e];
            int tiles = (c + 127) >> 7;
            for (int t = 0; t < tiles; t++) {
                g_tile_expert[nt] = e;
                g_tile_mbase[nt]  = e * T_TOK + t * 128;
                nt++;
            }
        }
        g_num_tiles = nt;
    }
    if (blockIdx.x < XBLK) {
        int i = blockIdx.x * 256 + threadIdx.x;
        int tok = i >> 9;
        int j = i & 511;
        float4 vv = ((const float4*)x)[(size_t)tok * 512 + j];
        uint32_t h0, u0, h1, u1;
        split2(vv.x, vv.y, h0, u0, 1.0f);
        split2(vv.z, vv.w, h1, u1, 1.0f);
        size_t rb = (size_t)tok * (KCAT / 4);           // uint2 units per row
        ((uint2*)g_xc)[rb + j]       = make_uint2(h0, h1);
        ((uint2*)g_xc)[rb + 512 + j] = make_uint2(u0, u1);
    } else {
        size_t i = (size_t)(blockIdx.x - XBLK) * 256 + threadIdx.x;
        int row = (int)(i >> 9);                        // e*HDIM + n
        int j = (int)(i & 511);
        float4 vv = ((const float4*)ew)[i];
        uint32_t h0, u0, h1, u1;
        // post=32 scales the correction term exactly (power of 2 in fp16)
        split2(vv.x * 64.f, vv.y * 64.f, h0, u0, 32.0f);
        split2(vv.z * 64.f, vv.w * 64.f, h1, u1, 32.0f);
        size_t rb = (size_t)row * (KCAT / 4);
        ((uint2*)g_wc)[rb + j]       = make_uint2(h0, h1);
        ((uint2*)g_wc)[rb + 512 + j] = make_uint2(u0, u1);
    }
}

// ============================================================================
// K3: grouped GEMM — 128x128xK4096 merged Ootomo, single fp32 acc set,
// 4 warps (2x2 grid, 64x64 warp tile), 2 CTAs/SM, 4-stage cp.async, SW64.
// Single __syncthreads per k-step; stage (kt+3)&3 was consumed in kt-1.
// A rows gathered per-token via s_token; 8 gmem pointers precomputed.
// Mid-loop: acc *= 31/32 (fp32-exact) between the xh*wh and u*32v halves.
// Epilogue: weighted rows -> ybuf (padding rows never read by combine).
// ============================================================================
#define MAT_B     8192                        // 128 rows x 64B
#define STAGE_B   (2 * MAT_B)                 // 16384 (A, B)
#define NSTAGE    4
#define SMEM_DYN  (1024 + NSTAGE * STAGE_B)   // 66560 B -> 2 CTAs/SM

__global__ void __launch_bounds__(128, 2)
moe_gemm_kernel() {
    int tile = blockIdx.y;
    if (tile >= g_num_tiles) return;
    int n0    = blockIdx.x * 128;
    int e     = g_tile_expert[tile];
    int mbase = g_tile_mbase[tile];

    extern __shared__ char dsm[];
    float* s_fr    = (float*)dsm;             // 128: slotw/64 per row
    int*   s_token = (int*)(dsm + 512);       // 128: token per row
    uint32_t st0 = smem_to_u32(dsm) + 1024;

    int tid = threadIdx.x, lane = tid & 31, wid = tid >> 5;
    int wm = wid >> 1, wn = wid & 1;          // 2x2 grid, warp 64(M)x64(N)

    if (tid < 128) {
        s_fr[tid]    = g_slot_w[mbase + tid] * (1.0f / 64.0f);
        s_token[tid] = g_slot_token[mbase + tid];
    }
    __syncthreads();

    const __half* Bg = g_wc + ((size_t)e * HDIM + n0) * KCAT;

    // precompute per-thread fill pointers (8 chunks: 4 A via token gather, 4 B)
    const __half* gsrc[8];
    uint32_t sdst[8];
#pragma unroll
    for (int i = 0; i < 8; i++) {
        int cid = tid + i * 128;
        int mat = cid >> 9;                   // 0=A, 1=B
        int win = cid & 511;
        int rr  = win >> 2;
        int cc  = win & 3;
        if (mat == 0) {
            int tok = s_token[rr];
            gsrc[i] = g_xc + (size_t)tok * KCAT + cc * 8;
        } else {
            gsrc[i] = Bg + (size_t)rr * KCAT + cc * 8;
        }
        sdst[i] = st0 + mat * MAT_B + SW64((uint32_t)(rr * 64 + cc * 16));
    }

    auto fill = [&](int stage, int kt) {
        uint32_t so = (uint32_t)(stage * STAGE_B);
        int k0 = kt * 32;
#pragma unroll
        for (int i = 0; i < 8; i++)
            CP_ASYNC16(sdst[i] + so, gsrc[i] + k0);
    };

    fill(0, 0); CP_COMMIT();
    fill(1, 1); CP_COMMIT();
    fill(2, 2); CP_COMMIT();

    float acc[4][8][4];
#pragma unroll
    for (int a = 0; a < 4; a++)
#pragma unroll
        for (int b = 0; b < 8; b++)
#pragma unroll
            for (int c = 0; c < 4; c++) acc[a][b][c] = 0.f;

    for (int kt = 0; kt < KSTEPS; kt++) {
        // between halves: acc = T1 -> scale by 31/32 (fp32-exact cancellation)
        if (kt == KSTEPS / 2) {
#pragma unroll
            for (int a = 0; a < 4; a++)
#pragma unroll
                for (int b = 0; b < 8; b++)
#pragma unroll
                    for (int c = 0; c < 4; c++) acc[a][b][c] *= 0.96875f;
        }
        CP_WAIT2();
        __syncthreads();                      // single sync per k-step

        int nxt = kt + 3;                     // stage (kt+3)&3 was read in kt-1
        if (nxt < KSTEPS) fill(nxt & 3, nxt);
        CP_COMMIT();

        uint32_t sbase = st0 + (kt & 3) * STAGE_B;
        uint32_t sA = sbase, sB = sbase + MAT_B;
#pragma unroll
        for (int k16 = 0; k16 < 2; k16++) {
            uint32_t af[4][4];
#pragma unroll
            for (int mi = 0; mi < 4; mi++) {
                uint32_t ad = SW64((uint32_t)(
                    (wm * 64 + mi * 16 + (lane & 15)) * 64
                    + k16 * 32 + (lane >> 4) * 16));
                ldsm_x4(af[mi], sA + ad);
            }
            uint32_t bf[4][4];
#pragma unroll
            for (int jj = 0; jj < 4; jj++) {
                uint32_t bd = SW64((uint32_t)(
                    (wn * 64 + jj * 16 + ((lane >> 4) << 3) + (lane & 7)) * 64
                    + k16 * 32 + (((lane >> 3) & 1) << 4)));
                ldsm_x4(bf[jj], sB + bd);
            }
            // 32 HMMAs per k16, acc reuse distance 32
#pragma unroll
            for (int mi = 0; mi < 4; mi++)
#pragma unroll
                for (int jj = 0; jj < 4; jj++)
#pragma unroll
                    for (int s = 0; s < 2; s++)
                        mma16816(acc[mi][jj * 2 + s], af[mi], &bf[jj][s * 2]);
        }
    }

    // epilogue: y = acc * slotw/64 -> ybuf
#pragma unroll
    for (int mi = 0; mi < 4; mi++) {
        int r0 = wm * 64 + mi * 16 + (lane >> 2);
        float f0 = s_fr[r0], f1 = s_fr[r0 + 8];
        size_t o0 = (size_t)(mbase + r0) * HDIM + n0;
#pragma unroll
        for (int n8 = 0; n8 < 8; n8++) {
            int c = wn * 64 + n8 * 8 + (lane & 3) * 2;
            *(float2*)(g_ybuf + o0 + c) =
                make_float2(acc[mi][n8][0] * f0, acc[mi][n8][1] * f0);
            *(float2*)(g_ybuf + o0 + (size_t)8 * HDIM + c) =
                make_float2(acc[mi][n8][2] * f1, acc[mi][n8][3] * f1);
        }
    }
}

// ============================================================================
// K4: combine — out[t] = ybuf[slot0(t)] + ybuf[slot1(t)]; block 0 also
// resets the cursors for the next launch (graph replay invariant).
// ============================================================================
__global__ void moe_combine_kernel(float* __restrict__ out) {
    if (blockIdx.x == 0 && threadIdx.x < NEXP) g_cursor[threadIdx.x] = 0;
    int i = blockIdx.x * blockDim.x + threadIdx.x;
    int t  = i >> 9;
    int h4 = i & 511;
    int s0 = g_tok_slot[2 * t + 0];
    int s1 = g_tok_slot[2 * t + 1];
    float4 a = *(const float4*)(g_ybuf + (size_t)s0 * HDIM + h4 * 4);
    float4 b = *(const float4*)(g_ybuf + (size_t)s1 * HDIM + h4 * 4);
    float4 o;
    o.x = a.x + b.x; o.y = a.y + b.y; o.z = a.z + b.z; o.w = a.w + b.w;
    ((float4*)out)[i] = o;
}

// ============================================================================
// Launch — 4 kernels total (was 7)
// ============================================================================
extern "C" void kernel_launch(void* const* d_in, const int* in_sizes, int n_in,
                              void* d_out, int out_size) {
    const float* x  = (const float*)d_in[0];   // hidden_states [T, H]
    const float* gw = (const float*)d_in[1];   // gate_w [E, H]
    const float* ew = (const float*)d_in[2];   // expert_w [E, H, H]
    float* out    = (float*)d_out;             // [T, H]
    float* logits = out + (size_t)T_TOK * HDIM;

    cudaFuncSetAttribute(moe_gemm_kernel,
                         cudaFuncAttributeMaxDynamicSharedMemorySize, SMEM_DYN);

    moe_router_kernel<<<(T_TOK * 32) / 256, 256>>>(x, gw, logits);
    moe_convert_kernel<<<XBLK + WBLK, 256>>>(x, ew);
    moe_gemm_kernel<<<dim3(16, MAX_TILES), 128, SMEM_DYN>>>();
    moe_combine_kernel<<<(T_TOK * (HDIM / 4)) / 256, 256>>>(out);
}

// round 13
// speedup vs baseline: 1.0332x; 1.0077x over previous
#include <cuda_runtime.h>
#include <cuda_fp16.h>
#include <cstdint>

// ============================================================================
// Problem constants
// ============================================================================
#define T_TOK   8192          // B*S tokens
#define HDIM    2048
#define NEXP    8
#define MAX_TILES 136         // sum ceil(count_e/128) <= 2T/128 + E
#define KCAT    4096          // merged K: [xh | u] / [wh | 32v]
#define KSTEPS  128           // KCAT / 32 per k-step
#define NSLOTF  (NEXP * T_TOK)   // fixed-capacity slot space (65536)

// ============================================================================
// PTX helpers — family-portable only (mma.sync / ldmatrix / cp.async)
// ============================================================================
__device__ __forceinline__ uint32_t smem_to_u32(const void* p) {
    uint32_t a;
    asm("{ .reg .u64 t; cvta.to.shared.u64 t, %1; cvt.u32.u64 %0, t; }"
        : "=r"(a) : "l"(p));
    return a;
}

#define CP_ASYNC16(smem, gmem) \
    asm volatile("cp.async.cg.shared.global [%0], [%1], 16;" \
        :: "r"(smem), "l"(gmem))
#define CP_COMMIT() asm volatile("cp.async.commit_group;" ::: "memory")
#define CP_WAIT2()  asm volatile("cp.async.wait_group 2;" ::: "memory")

__device__ __forceinline__ void ldsm_x4(uint32_t* r, uint32_t addr) {
    asm volatile("ldmatrix.sync.aligned.m8n8.x4.shared.b16 {%0,%1,%2,%3}, [%4];"
        : "=r"(r[0]), "=r"(r[1]), "=r"(r[2]), "=r"(r[3]) : "r"(addr));
}

// m16n8k16 fp16 HMMA, fp32 accumulate
__device__ __forceinline__ void mma16816(float* d, const uint32_t* a,
                                         const uint32_t* b) {
    asm volatile(
        "mma.sync.aligned.m16n8k16.row.col.f32.f16.f16.f32 "
        "{%0,%1,%2,%3}, {%4,%5,%6,%7}, {%8,%9}, {%0,%1,%2,%3};"
        : "+f"(d[0]), "+f"(d[1]), "+f"(d[2]), "+f"(d[3])
        : "r"(a[0]), "r"(a[1]), "r"(a[2]), "r"(a[3]), "r"(b[0]), "r"(b[1]));
}

// SW64 swizzle: XOR byte-offset bits[5:4] with bits[8:7] (row bits for 64B rows)
#define SW64(off) ((off) ^ (((off) >> 3) & 0x30))

// ============================================================================
// Device scratch — fixed-capacity slot layout: slot = e*T_TOK + pos.
// g_cursor must be 0 on entry of every launch: zero-init covers call 1;
// the combine kernel clears it at the end of each launch (graph-replay safe,
// deterministic — routing depends only on inputs).
// ============================================================================
__device__ int    g_cursor[NEXP];
__device__ int    g_slot_token[NSLOTF];    // zero-init; stale values stay in
__device__ float  g_slot_w[NSLOTF];        //   [0,T) so always a valid index
__device__ int    g_tok_slot[T_TOK * 2];

__device__ __half g_xc[(size_t)T_TOK * KCAT];              // 67 MB [xh | u], per TOKEN
__device__ __half g_wc[(size_t)NEXP * HDIM * KCAT];        // 134 MB [wh | 32v]
__device__ float  g_ybuf[(size_t)NSLOTF * HDIM];           // 536 MB, sparse-written

// ============================================================================
// K1: fused prep — router blocks + x split-convert + w split-convert.
// All three ranges are data-independent (per-token x layout; fixed-capacity
// slots remove the scan). Router's compute hides under convert's DRAM time.
//
// Ootomo split:
//   A row (4096): [ xh = fp16(x) | u = fp16(xh/32 + (x-xh)) ]
//   B row (4096): [ wh = fp16(64w) | 32*fp16(wh/32 + (64w-wh)) ]  (32x exact)
// ============================================================================
#define RBLK (T_TOK / 8)                          // 1024 router blocks (8 warps)
#define XBLK (T_TOK * 512 / 256)                  // 16384
#define WBLK (NEXP * HDIM * HDIM / 4 / 256)       // 32768

__device__ __forceinline__ void split2(float a, float b, uint32_t& h,
                                       uint32_t& u, float post) {
    __half2 hh = __floats2half2_rn(a, b);
    float2 hf = __half22float2(hh);
    __half2 uu = __floats2half2_rn((hf.x * 0.03125f + (a - hf.x)) * post,
                                   (hf.y * 0.03125f + (b - hf.y)) * post);
    h = *(uint32_t*)&hh;
    u = *(uint32_t*)&uu;
}

__global__ void moe_prep_kernel(const float* __restrict__ x,
                                const float* __restrict__ gw,
                                const float* __restrict__ ew,
                                float* __restrict__ logits_out) {
    if (blockIdx.x < RBLK) {
        // ---- router: one warp per token ----
        int warp = blockIdx.x * 8 + (threadIdx.x >> 5);
        int lane = threadIdx.x & 31;
        const float4* xr = (const float4*)(x + (size_t)warp * HDIM);
        float acc[NEXP];
#pragma unroll
        for (int e = 0; e < NEXP; e++) acc[e] = 0.f;
        for (int i = lane; i < HDIM / 4; i += 32) {
            float4 xv = xr[i];
#pragma unroll
            for (int e = 0; e < NEXP; e++) {
                float4 gv = ((const float4*)(gw + e * HDIM))[i];
                acc[e] += xv.x * gv.x + xv.y * gv.y + xv.z * gv.z + xv.w * gv.w;
            }
        }
#pragma unroll
        for (int e = 0; e < NEXP; e++)
#pragma unroll
            for (int off = 16; off; off >>= 1)
                acc[e] += __shfl_xor_sync(0xFFFFFFFFu, acc[e], off);
        if (lane == 0) {
#pragma unroll
            for (int e = 0; e < NEXP; e++) logits_out[warp * NEXP + e] = acc[e];
            int i1 = 0; float l1 = acc[0];
#pragma unroll
            for (int e = 1; e < NEXP; e++) if (acc[e] > l1) { l1 = acc[e]; i1 = e; }
            int i2 = -1; float l2 = -3.4e38f;
#pragma unroll
            for (int e = 0; e < NEXP; e++)
                if (e != i1 && acc[e] > l2) { l2 = acc[e]; i2 = e; }
            float ex = expf(l2 - l1);
            float w1 = 1.0f / (1.0f + ex);
            float w2 = ex / (1.0f + ex);
            int p1 = atomicAdd(&g_cursor[i1], 1);
            int s1 = i1 * T_TOK + p1;
            g_slot_token[s1] = warp;  g_slot_w[s1] = w1;
            g_tok_slot[warp * 2] = s1;
            int p2 = atomicAdd(&g_cursor[i2], 1);
            int s2 = i2 * T_TOK + p2;
            g_slot_token[s2] = warp;  g_slot_w[s2] = w2;
            g_tok_slot[warp * 2 + 1] = s2;
        }
    } else if (blockIdx.x < RBLK + XBLK) {
        // ---- x split-convert (per TOKEN layout) ----
        int i = (blockIdx.x - RBLK) * 256 + threadIdx.x;
        int tok = i >> 9;
        int j = i & 511;
        float4 vv = ((const float4*)x)[(size_t)tok * 512 + j];
        uint32_t h0, u0, h1, u1;
        split2(vv.x, vv.y, h0, u0, 1.0f);
        split2(vv.z, vv.w, h1, u1, 1.0f);
        size_t rb = (size_t)tok * (KCAT / 4);           // uint2 units per row
        ((uint2*)g_xc)[rb + j]       = make_uint2(h0, h1);
        ((uint2*)g_xc)[rb + 512 + j] = make_uint2(u0, u1);
    } else {
        // ---- w split-convert ----
        size_t i = (size_t)(blockIdx.x - RBLK - XBLK) * 256 + threadIdx.x;
        int row = (int)(i >> 9);                        // e*HDIM + n
        int j = (int)(i & 511);
        float4 vv = ((const float4*)ew)[i];
        uint32_t h0, u0, h1, u1;
        // post=32 scales the correction term exactly (power of 2 in fp16)
        split2(vv.x * 64.f, vv.y * 64.f, h0, u0, 32.0f);
        split2(vv.z * 64.f, vv.w * 64.f, h1, u1, 32.0f);
        size_t rb = (size_t)row * (KCAT / 4);
        ((uint2*)g_wc)[rb + j]       = make_uint2(h0, h1);
        ((uint2*)g_wc)[rb + 512 + j] = make_uint2(u0, u1);
    }
}

// ============================================================================
// K2: grouped GEMM — 128x128xK4096 merged Ootomo, single fp32 acc set,
// 4 warps (2x2 grid, 64x64 warp tile), 2 CTAs/SM, 4-stage cp.async, SW64.
// Self-scheduling: each CTA derives (expert, mbase) from g_cursor with an
// 8-step prefix walk (no tile map, no scan kernel).
// Single __syncthreads per k-step; stage (kt+3)&3 was consumed in kt-1.
// Mid-loop: acc *= 31/32 (fp32-exact) between the xh*wh and u*32v halves.
// Epilogue: weighted rows -> ybuf (padding rows never read by combine).
// ============================================================================
#define MAT_B     8192                        // 128 rows x 64B
#define STAGE_B   (2 * MAT_B)                 // 16384 (A, B)
#define NSTAGE    4
#define SMEM_DYN  (1024 + NSTAGE * STAGE_B)   // 66560 B -> 2 CTAs/SM

__global__ void __launch_bounds__(128, 2)
moe_gemm_kernel() {
    // per-CTA tile schedule from cursors (8 L2-hot ints)
    int tile = blockIdx.y;
    int e = -1, mbase = 0, nt = 0;
#pragma unroll
    for (int ee = 0; ee < NEXP; ee++) {
        int tiles = (g_cursor[ee] + 127) >> 7;
        if (e < 0 && tile < nt + tiles) {
            e = ee;
            mbase = ee * T_TOK + (tile - nt) * 128;
        }
        nt += tiles;
    }
    if (e < 0) return;
    int n0 = blockIdx.x * 128;

    extern __shared__ char dsm[];
    float* s_fr    = (float*)dsm;             // 128: slotw/64 per row
    int*   s_token = (int*)(dsm + 512);       // 128: token per row
    uint32_t st0 = smem_to_u32(dsm) + 1024;

    int tid = threadIdx.x, lane = tid & 31, wid = tid >> 5;
    int wm = wid >> 1, wn = wid & 1;          // 2x2 grid, warp 64(M)x64(N)

    if (tid < 128) {
        s_fr[tid]    = g_slot_w[mbase + tid] * (1.0f / 64.0f);
        s_token[tid] = g_slot_token[mbase + tid];
    }
    __syncthreads();

    const __half* Bg = g_wc + ((size_t)e * HDIM + n0) * KCAT;

    // precompute per-thread fill pointers (8 chunks: 4 A via token gather, 4 B)
    const __half* gsrc[8];
    uint32_t sdst[8];
#pragma unroll
    for (int i = 0; i < 8; i++) {
        int cid = tid + i * 128;
        int mat = cid >> 9;                   // 0=A, 1=B
        int win = cid & 511;
        int rr  = win >> 2;
        int cc  = win & 3;
        if (mat == 0) {
            int tok = s_token[rr];
            gsrc[i] = g_xc + (size_t)tok * KCAT + cc * 8;
        } else {
            gsrc[i] = Bg + (size_t)rr * KCAT + cc * 8;
        }
        sdst[i] = st0 + mat * MAT_B + SW64((uint32_t)(rr * 64 + cc * 16));
    }

    auto fill = [&](int stage, int kt) {
        uint32_t so = (uint32_t)(stage * STAGE_B);
        int k0 = kt * 32;
#pragma unroll
        for (int i = 0; i < 8; i++)
            CP_ASYNC16(sdst[i] + so, gsrc[i] + k0);
    };

    fill(0, 0); CP_COMMIT();
    fill(1, 1); CP_COMMIT();
    fill(2, 2); CP_COMMIT();

    float acc[4][8][4];
#pragma unroll
    for (int a = 0; a < 4; a++)
#pragma unroll
        for (int b = 0; b < 8; b++)
#pragma unroll
            for (int c = 0; c < 4; c++) acc[a][b][c] = 0.f;

    for (int kt = 0; kt < KSTEPS; kt++) {
        // between halves: acc = T1 -> scale by 31/32 (fp32-exact cancellation)
        if (kt == KSTEPS / 2) {
#pragma unroll
            for (int a = 0; a < 4; a++)
#pragma unroll
                for (int b = 0; b < 8; b++)
#pragma unroll
                    for (int c = 0; c < 4; c++) acc[a][b][c] *= 0.96875f;
        }
        CP_WAIT2();
        __syncthreads();                      // single sync per k-step

        int nxt = kt + 3;                     // stage (kt+3)&3 was read in kt-1
        if (nxt < KSTEPS) fill(nxt & 3, nxt);
        CP_COMMIT();

        uint32_t sbase = st0 + (kt & 3) * STAGE_B;
        uint32_t sA = sbase, sB = sbase + MAT_B;
#pragma unroll
        for (int k16 = 0; k16 < 2; k16++) {
            uint32_t af[4][4];
#pragma unroll
            for (int mi = 0; mi < 4; mi++) {
                uint32_t ad = SW64((uint32_t)(
                    (wm * 64 + mi * 16 + (lane & 15)) * 64
                    + k16 * 32 + (lane >> 4) * 16));
                ldsm_x4(af[mi], sA + ad);
            }
            uint32_t bf[4][4];
#pragma unroll
            for (int jj = 0; jj < 4; jj++) {
                uint32_t bd = SW64((uint32_t)(
                    (wn * 64 + jj * 16 + ((lane >> 4) << 3) + (lane & 7)) * 64
                    + k16 * 32 + (((lane >> 3) & 1) << 4)));
                ldsm_x4(bf[jj], sB + bd);
            }
            // 32 HMMAs per k16, acc reuse distance 32
#pragma unroll
            for (int mi = 0; mi < 4; mi++)
#pragma unroll
                for (int jj = 0; jj < 4; jj++)
#pragma unroll
                    for (int s = 0; s < 2; s++)
                        mma16816(acc[mi][jj * 2 + s], af[mi], &bf[jj][s * 2]);
        }
    }

    // epilogue: y = acc * slotw/64 -> ybuf
#pragma unroll
    for (int mi = 0; mi < 4; mi++) {
        int r0 = wm * 64 + mi * 16 + (lane >> 2);
        float f0 = s_fr[r0], f1 = s_fr[r0 + 8];
        size_t o0 = (size_t)(mbase + r0) * HDIM + n0;
#pragma unroll
        for (int n8 = 0; n8 < 8; n8++) {
            int c = wn * 64 + n8 * 8 + (lane & 3) * 2;
            *(float2*)(g_ybuf + o0 + c) =
                make_float2(acc[mi][n8][0] * f0, acc[mi][n8][1] * f0);
            *(float2*)(g_ybuf + o0 + (size_t)8 * HDIM + c) =
                make_float2(acc[mi][n8][2] * f1, acc[mi][n8][3] * f1);
        }
    }
}

// ============================================================================
// K3: combine — out[t] = ybuf[slot0(t)] + ybuf[slot1(t)]; block 0 also
// resets the cursors for the next launch (graph replay invariant; runs
// after the GEMM's g_cursor reads).
// ============================================================================
__global__ void moe_combine_kernel(float* __restrict__ out) {
    if (blockIdx.x == 0 && threadIdx.x < NEXP) g_cursor[threadIdx.x] = 0;
    int i = blockIdx.x * blockDim.x + threadIdx.x;
    int t  = i >> 9;
    int h4 = i & 511;
    int s0 = g_tok_slot[2 * t + 0];
    int s1 = g_tok_slot[2 * t + 1];
    float4 a = *(const float4*)(g_ybuf + (size_t)s0 * HDIM + h4 * 4);
    float4 b = *(const float4*)(g_ybuf + (size_t)s1 * HDIM + h4 * 4);
    float4 o;
    o.x = a.x + b.x; o.y = a.y + b.y; o.z = a.z + b.z; o.w = a.w + b.w;
    ((float4*)out)[i] = o;
}

// ============================================================================
// Launch — 3 kernels total (was 4)
// ============================================================================
extern "C" void kernel_launch(void* const* d_in, const int* in_sizes, int n_in,
                              void* d_out, int out_size) {
    const float* x  = (const float*)d_in[0];   // hidden_states [T, H]
    const float* gw = (const float*)d_in[1];   // gate_w [E, H]
    const float* ew = (const float*)d_in[2];   // expert_w [E, H, H]
    float* out    = (float*)d_out;             // [T, H]
    float* logits = out + (size_t)T_TOK * HDIM;

    cudaFuncSetAttribute(moe_gemm_kernel,
                         cudaFuncAttributeMaxDynamicSharedMemorySize, SMEM_DYN);

    moe_prep_kernel<<<RBLK + XBLK + WBLK, 256>>>(x, gw, ew, logits);
    moe_gemm_kernel<<<dim3(16, MAX_TILES), 128, SMEM_DYN>>>();
    moe_combine_kernel<<<(T_TOK * (HDIM / 4)) / 256, 256>>>(out);
}